// round 10
// baseline (speedup 1.0000x reference)
#include <cuda_runtime.h>
#include <cstdint>

// result = sum_j W[j] * S_j / T_j
//   T_j = sum_n y_true[n][j],  S_j = sum_n |y_true[n][j] - y_preds[n][j]|
//
// Warp-specialized hybrid: warps 0-9 run a 4-stage cp.async.bulk (TMA)
// pipeline over 57.8% of the data (named-barrier synced, so the other warps
// never wait on it); warps 10-19 run an independent unroll-3 LDG.128
// streaming loop over the remaining 42.2%. Both request engines run at
// their solo rates concurrently instead of being pacing-coupled.

__device__ float g_T[5] = {0.f, 0.f, 0.f, 0.f, 0.f};
__device__ float g_S[5] = {0.f, 0.f, 0.f, 0.f, 0.f};
__device__ unsigned int g_count = 0;

__constant__ float c_W[5] = {0.3f, 0.175f, 0.175f, 0.175f, 0.175f};

#define NSTAGES      4
#define NTHREADS     640
#define TMA_THREADS  320                   // warps 0-9
#define LDG_THREADS  320                   // warps 10-19
#define CHUNK_FLOATS 2560                  // TMA chunk; % 5 == 0
#define CHUNK_BYTES  (CHUNK_FLOATS * 4)    // 10240
#define STAGE_BYTES  (2 * CHUNK_BYTES)     // 20480
#define SMEM_BYTES   (NSTAGES * STAGE_BYTES)  // 81920 -> 2 blocks/SM
#define NBLOCKS      296
#define LDG_TOT      (NBLOCKS * LDG_THREADS)  // 94720, % 5 == 0

static __device__ __forceinline__ uint32_t s2u(const void* p) {
    return (uint32_t)__cvta_generic_to_shared(p);
}

static __device__ __forceinline__ void mbar_init(uint32_t mbar, uint32_t count) {
    asm volatile("mbarrier.init.shared.b64 [%0], %1;" :: "r"(mbar), "r"(count) : "memory");
}

static __device__ __forceinline__ void mbar_wait(uint32_t mbar, uint32_t phase) {
    uint32_t done;
    asm volatile(
        "{\n\t.reg .pred p;\n\t"
        "mbarrier.try_wait.parity.acquire.cta.shared::cta.b64 p, [%1], %2;\n\t"
        "selp.b32 %0, 1, 0, p;\n\t}"
        : "=r"(done) : "r"(mbar), "r"(phase) : "memory");
    while (!done) {
        asm volatile(
            "{\n\t.reg .pred p;\n\t"
            "mbarrier.try_wait.parity.acquire.cta.shared::cta.b64 p, [%1], %2, 0x989680;\n\t"
            "selp.b32 %0, 1, 0, p;\n\t}"
            : "=r"(done) : "r"(mbar), "r"(phase) : "memory");
    }
}

static __device__ __forceinline__ void issue_chunk(
    const char* __restrict__ yt, const char* __restrict__ yp,
    uint32_t stage_smem, uint32_t mbar, long long byte_off)
{
    asm volatile("mbarrier.arrive.expect_tx.shared.b64 _, [%0], %1;"
                 :: "r"(mbar), "r"((uint32_t)STAGE_BYTES) : "memory");
    asm volatile(
        "cp.async.bulk.shared::cluster.global.mbarrier::complete_tx::bytes [%0], [%1], %2, [%3];"
        :: "r"(stage_smem), "l"(yt + byte_off), "r"((uint32_t)CHUNK_BYTES), "r"(mbar) : "memory");
    asm volatile(
        "cp.async.bulk.shared::cluster.global.mbarrier::complete_tx::bytes [%0], [%1], %2, [%3];"
        :: "r"(stage_smem + CHUNK_BYTES), "l"(yp + byte_off), "r"((uint32_t)CHUNK_BYTES), "r"(mbar) : "memory");
}

// Rotate 4 slot-accumulators (slot k holds column (c0+k)%5) into absolute cols.
#define ROT_CASE(C)                                                           \
    case C:                                                                   \
        cT[(C+0)%5]=AT[0]; cT[(C+1)%5]=AT[1]; cT[(C+2)%5]=AT[2];              \
        cT[(C+3)%5]=AT[3]; cT[(C+4)%5]=0.f;                                   \
        cS[(C+0)%5]=AS[0]; cS[(C+1)%5]=AS[1]; cS[(C+2)%5]=AS[2];              \
        cS[(C+3)%5]=AS[3]; cS[(C+4)%5]=0.f;                                   \
        break;

__global__ void __launch_bounds__(NTHREADS, 2) fused_loss_ws_kernel(
    const char* __restrict__ yt,
    const char* __restrict__ yp,
    int n_floats,
    float* __restrict__ out)
{
    extern __shared__ char dynbuf[];
    __shared__ unsigned long long full_bar[NSTAGES];
    __shared__ float sT[5];
    __shared__ float sS[5];
    __shared__ bool is_last;

    const int tid = threadIdx.x;
    const int bid = blockIdx.x;

    // --- split: TMA covers [0, n_tma), LDG covers the rest ---
    // ~57.8%, rounded DOWN to a multiple of NBLOCKS chunks (uniform cnt).
    // Real input: 4736 chunks = 296*16, n_tma = 12,124,160 (0 mod 20).
    int nchunks = (int)((((long long)n_floats * 604) >> 10) / CHUNK_FLOATS);
    nchunks = (nchunks / NBLOCKS) * NBLOCKS;
    const int max_chunks = (n_floats / CHUNK_FLOATS / NBLOCKS) * NBLOCKS;
    if (nchunks > max_chunks) nchunks = max_chunks;
    const int n_tma = nchunks * CHUNK_FLOATS;
    const int cnt   = nchunks / NBLOCKS;                // block-uniform

    if (tid == 0) {
        #pragma unroll
        for (int s = 0; s < NSTAGES; s++) mbar_init(s2u(&full_bar[s]), 1);
    }
    if (tid < 5) { sT[tid] = 0.f; sS[tid] = 0.f; }
    __syncthreads();

    // Slot accumulators; phase c0 = (4 * (tid mod 320)) % 5 for both groups
    // (chunk starts, n_tma/4, both strides, and 320 are all 0 mod 5).
    float AT[4] = {0.f, 0.f, 0.f, 0.f};
    float AS[4] = {0.f, 0.f, 0.f, 0.f};

    if (tid < TMA_THREADS) {
        // ================= TMA engine (warps 0-9) =================
        if (tid == 0) {
            const int pro = (cnt < NSTAGES) ? cnt : NSTAGES;
            for (int l = 0; l < pro; l++) {
                const long long c = (long long)bid + (long long)l * NBLOCKS;
                issue_chunk(yt, yp, s2u(dynbuf) + l * STAGE_BYTES, s2u(&full_bar[l]),
                            c * (long long)CHUNK_BYTES);
            }
        }
        for (int l = 0; l < cnt; l++) {
            const int s  = l & (NSTAGES - 1);
            const int ph = (l >> 2) & 1;
            mbar_wait(s2u(&full_bar[s]), ph);

            const float4* ts = (const float4*)(dynbuf + s * STAGE_BYTES);
            const float4* ps = (const float4*)(dynbuf + s * STAGE_BYTES + CHUNK_BYTES);
            // Two float4s per thread, stride 320 apart: both have phase c0.
            const float4 t0 = ts[tid], t1 = ts[tid + TMA_THREADS];
            const float4 p0 = ps[tid], p1 = ps[tid + TMA_THREADS];

            AT[0] += t0.x; AS[0] += fabsf(t0.x - p0.x);
            AT[1] += t0.y; AS[1] += fabsf(t0.y - p0.y);
            AT[2] += t0.z; AS[2] += fabsf(t0.z - p0.z);
            AT[3] += t0.w; AS[3] += fabsf(t0.w - p0.w);
            AT[0] += t1.x; AS[0] += fabsf(t1.x - p1.x);
            AT[1] += t1.y; AS[1] += fabsf(t1.y - p1.y);
            AT[2] += t1.z; AS[2] += fabsf(t1.z - p1.z);
            AT[3] += t1.w; AS[3] += fabsf(t1.w - p1.w);

            // Named barrier over the TMA group only — LDG warps unaffected.
            asm volatile("bar.sync 1, %0;" :: "n"(TMA_THREADS) : "memory");

            if (tid == 0 && l + NSTAGES < cnt) {
                const long long c = (long long)bid + (long long)(l + NSTAGES) * NBLOCKS;
                issue_chunk(yt, yp, s2u(dynbuf) + s * STAGE_BYTES, s2u(&full_bar[s]),
                            c * (long long)CHUNK_BYTES);
            }
        }
    } else {
        // ================= LDG engine (warps 10-19) =================
        const int lgid   = bid * LDG_THREADS + (tid - TMA_THREADS);
        const int start4 = n_tma / 4;                   // 0 mod 5
        const int end4   = n_floats / 4;
        const float4* yt4 = (const float4*)yt;
        const float4* yp4 = (const float4*)yp;

        int i4 = start4 + lgid;
        // Unroll-3: 6 independent LDG.128 in flight, front-batched.
        for (; i4 + 2 * LDG_TOT < end4; i4 += 3 * LDG_TOT) {
            float4 t0 = __ldcs(yt4 + i4);
            float4 t1 = __ldcs(yt4 + i4 + LDG_TOT);
            float4 t2 = __ldcs(yt4 + i4 + 2 * LDG_TOT);
            float4 p0 = __ldcs(yp4 + i4);
            float4 p1 = __ldcs(yp4 + i4 + LDG_TOT);
            float4 p2 = __ldcs(yp4 + i4 + 2 * LDG_TOT);

            AT[0] += t0.x; AS[0] += fabsf(t0.x - p0.x);
            AT[1] += t0.y; AS[1] += fabsf(t0.y - p0.y);
            AT[2] += t0.z; AS[2] += fabsf(t0.z - p0.z);
            AT[3] += t0.w; AS[3] += fabsf(t0.w - p0.w);
            AT[0] += t1.x; AS[0] += fabsf(t1.x - p1.x);
            AT[1] += t1.y; AS[1] += fabsf(t1.y - p1.y);
            AT[2] += t1.z; AS[2] += fabsf(t1.z - p1.z);
            AT[3] += t1.w; AS[3] += fabsf(t1.w - p1.w);
            AT[0] += t2.x; AS[0] += fabsf(t2.x - p2.x);
            AT[1] += t2.y; AS[1] += fabsf(t2.y - p2.y);
            AT[2] += t2.z; AS[2] += fabsf(t2.z - p2.z);
            AT[3] += t2.w; AS[3] += fabsf(t2.w - p2.w);
        }
        for (; i4 < end4; i4 += LDG_TOT) {
            float4 t = __ldcs(yt4 + i4);
            float4 p = __ldcs(yp4 + i4);
            AT[0] += t.x; AS[0] += fabsf(t.x - p.x);
            AT[1] += t.y; AS[1] += fabsf(t.y - p.y);
            AT[2] += t.z; AS[2] += fabsf(t.z - p.z);
            AT[3] += t.w; AS[3] += fabsf(t.w - p.w);
        }
    }

    // ================= epilogue (all threads) =================
    float cT[5], cS[5];
    const int gt = (tid < TMA_THREADS) ? tid : (tid - TMA_THREADS);
    const int c0 = (gt * 4) % 5;
    switch (c0) {
        ROT_CASE(0) ROT_CASE(1) ROT_CASE(2) ROT_CASE(3) ROT_CASE(4)
        default: break;
    }

    #pragma unroll
    for (int off = 16; off > 0; off >>= 1) {
        #pragma unroll
        for (int j = 0; j < 5; j++) {
            cT[j] += __shfl_xor_sync(0xffffffffu, cT[j], off);
            cS[j] += __shfl_xor_sync(0xffffffffu, cS[j], off);
        }
    }
    if ((tid & 31) == 0) {
        #pragma unroll
        for (int j = 0; j < 5; j++) {
            atomicAdd(&sT[j], cT[j]);
            atomicAdd(&sS[j], cS[j]);
        }
    }
    __syncthreads();

    // Scalar leftover (none for the real input; correctness guard).
    const int rem_start = (n_floats / 4) * 4;
    if (bid == 0 && tid == 0 && rem_start < n_floats) {
        const float* ytf = (const float*)yt;
        const float* ypf = (const float*)yp;
        for (int idx = rem_start; idx < n_floats; idx++) {
            const int c = idx % 5;
            atomicAdd(&g_T[c], ytf[idx]);
            atomicAdd(&g_S[c], fabsf(ytf[idx] - ypf[idx]));
        }
    }

    if (tid < 5) {
        atomicAdd(&g_T[tid], sT[tid]);
        atomicAdd(&g_S[tid], sS[tid]);
    }
    __threadfence();

    if (tid == 0) {
        const unsigned int c = atomicAdd(&g_count, 1u);
        is_last = (c == gridDim.x - 1);
    }
    __syncthreads();

    if (is_last && tid == 0) {
        float r = 0.f;
        #pragma unroll
        for (int j = 0; j < 5; j++) {
            const float T = atomicAdd(&g_T[j], 0.f);
            const float S = atomicAdd(&g_S[j], 0.f);
            r += c_W[j] * S / T;
        }
        out[0] = r;
        #pragma unroll
        for (int j = 0; j < 5; j++) { g_T[j] = 0.f; g_S[j] = 0.f; }
        g_count = 0u;
        __threadfence();
    }
}

extern "C" void kernel_launch(void* const* d_in, const int* in_sizes, int n_in,
                              void* d_out, int out_size) {
    const char* yt = (const char*)d_in[0];
    const char* yp = (const char*)d_in[1];
    float* out = (float*)d_out;
    const int n = in_sizes[0];   // 20971520 floats

    static bool attr_set = false;
    if (!attr_set) {
        cudaFuncSetAttribute(fused_loss_ws_kernel,
                             cudaFuncAttributeMaxDynamicSharedMemorySize, SMEM_BYTES);
        attr_set = true;
    }

    fused_loss_ws_kernel<<<NBLOCKS, NTHREADS, SMEM_BYTES>>>(yt, yp, n, out);
}